// round 9
// baseline (speedup 1.0000x reference)
#include <cuda_runtime.h>
#include <cstdint>

#define T_ 512
#define B_ 256
#define D_ 128
#define H_ 256
#define P_ 128
#define M_ (T_*B_)
#define NBLK 128
#define NTHR 256
#define BH_ (B_*H_)
#define NGRP 32
#define GBLK 4

typedef unsigned long long ull;

// ---------------- scratch ---------------------------------------------------
__device__ float g_A[(size_t)T_*B_*P_];          // precomputed x-part of distance
__device__ float g_xsq[M_];
__device__ float g_psum[P_];

// ---------------- f32x2 / ptx helpers --------------------------------------
__device__ __forceinline__ ull pack2(float lo, float hi) {
    ull r; asm("mov.b64 %0, {%1, %2};" : "=l"(r) : "f"(lo), "f"(hi)); return r;
}
__device__ __forceinline__ void unpack2(ull v, float& lo, float& hi) {
    asm("mov.b64 {%0, %1}, %2;" : "=f"(lo), "=f"(hi) : "l"(v));
}
__device__ __forceinline__ ull fma2(ull a, ull b, ull c) {
    ull d; asm("fma.rn.f32x2 %0, %1, %2, %3;" : "=l"(d) : "l"(a), "l"(b), "l"(c));
    return d;
}
__device__ __forceinline__ float sigf(float x) {
    return __fdividef(1.f, 1.f + __expf(-x));
}
__device__ __forceinline__ float tanh_fast(float x) {
    float e = __expf(2.f * x);
    return 1.f - __fdividef(2.f, e + 1.f);
}
__device__ __forceinline__ uint32_t smem_u32(const void* p) {
    uint32_t a;
    asm("{ .reg .u64 t; cvta.to.shared.u64 t, %1; cvt.u32.u64 %0, t; }"
        : "=r"(a) : "l"(p));
    return a;
}
__device__ __forceinline__ uint32_t mapa_u32(uint32_t a, uint32_t rank) {
    uint32_t d;
    asm("mapa.shared::cluster.u32 %0, %1, %2;" : "=r"(d) : "r"(a), "r"(rank));
    return d;
}
#define MBAR_INIT(addr, cnt) \
    asm volatile("mbarrier.init.shared.b64 [%0], %1;" :: "r"(addr), "r"(cnt) : "memory")
#define MBAR_ARRIVE_REMOTE(addr) \
    asm volatile("mbarrier.arrive.release.cluster.shared::cluster.b64 _, [%0];" \
                 :: "r"(addr) : "memory")
#define CLUSTER_SYNC() do { \
    asm volatile("barrier.cluster.arrive.aligned;" ::: "memory"); \
    asm volatile("barrier.cluster.wait.aligned;" ::: "memory"); } while (0)

__device__ __forceinline__ void mbar_wait_cluster(uint32_t addr, unsigned parity) {
    unsigned done;
    asm volatile(
        "{\n\t.reg .pred p;\n\t"
        "mbarrier.try_wait.parity.acquire.cluster.shared::cta.b64 p, [%1], %2, 0x989680;\n\t"
        "selp.b32 %0, 1, 0, p;\n\t}"
        : "=r"(done) : "r"(addr), "r"(parity) : "memory");
    if (!done) {
        asm volatile(
            "{\n\t.reg .pred P1;\n\t"
            "WL_%=:\n\t"
            "mbarrier.try_wait.parity.acquire.cluster.shared::cta.b64 P1, [%0], %1, 0x989680;\n\t"
            "@P1 bra.uni WD_%=;\n\t"
            "bra.uni WL_%=;\n\t"
            "WD_%=:\n\t}"
            :: "r"(addr), "r"(parity) : "memory");
    }
}

// ---------------- precompute: row norms of x -------------------------------
__global__ void xsq_kernel(const float* __restrict__ x) {
    int warp = (blockIdx.x * blockDim.x + threadIdx.x) >> 5;
    int lane = threadIdx.x & 31;
    if (warp >= M_) return;
    const float* row = x + (size_t)warp * D_;
    float s = 0.f;
#pragma unroll
    for (int i = 0; i < 4; i++) { float v = row[lane + 32*i]; s += v*v; }
#pragma unroll
    for (int o = 16; o; o >>= 1) s += __shfl_down_sync(0xffffffffu, s, o);
    if (lane == 0) g_xsq[warp] = s;
}

// ---------------- precompute: full row norms of prototypes -----------------
__global__ void psum_kernel(const float* __restrict__ proto) {
    int p = threadIdx.x;
    if (p >= P_) return;
    const float* row = proto + (size_t)p * (D_ + H_);
    float s = 0.f;
    for (int i = 0; i < D_ + H_; i++) { float v = row[i]; s += v*v; }
    g_psum[p] = s;
}

// ---------------- precompute GEMM: A[t,b,p] = xsq + psum - 2*x.px ----------
__global__ void agemm_kernel(const float* __restrict__ x,
                             const float* __restrict__ proto) {
    __shared__ float sX[64][33];
    __shared__ float sP[32][132];
    const int tid = threadIdx.x;
    const int tx = tid & 31;
    const int ty = tid >> 5;
    const int m0 = blockIdx.x * 64;

    float acc[8][4];
#pragma unroll
    for (int r = 0; r < 8; r++)
#pragma unroll
        for (int q = 0; q < 4; q++) acc[r][q] = 0.f;

    for (int k0 = 0; k0 < D_; k0 += 32) {
#pragma unroll
        for (int i = 0; i < 8; i++) {
            int e = tid + i * 256;
            int r = e >> 5, c = e & 31;
            sX[r][c] = x[(size_t)(m0 + r) * D_ + k0 + c];
        }
#pragma unroll
        for (int i = 0; i < 16; i++) {
            int e = tid + i * 256;
            int p = e >> 5, c = e & 31;
            sP[c][p] = proto[(size_t)p * (D_ + H_) + k0 + c];
        }
        __syncthreads();
#pragma unroll
        for (int kc = 0; kc < 32; kc++) {
            float4 b4 = *(const float4*)&sP[kc][tx * 4];
#pragma unroll
            for (int r = 0; r < 8; r++) {
                float a = sX[ty * 8 + r][kc];
                acc[r][0] += a * b4.x; acc[r][1] += a * b4.y;
                acc[r][2] += a * b4.z; acc[r][3] += a * b4.w;
            }
        }
        __syncthreads();
    }
#pragma unroll
    for (int r = 0; r < 8; r++) {
        int row = m0 + ty * 8 + r;
        float xs = g_xsq[row];
        float4 o;
        o.x = xs + g_psum[tx*4+0] - 2.f * acc[r][0];
        o.y = xs + g_psum[tx*4+1] - 2.f * acc[r][1];
        o.z = xs + g_psum[tx*4+2] - 2.f * acc[r][2];
        o.w = xs + g_psum[tx*4+3] - 2.f * acc[r][3];
        *(float4*)&g_A[(size_t)row * P_ + tx * 4] = o;
    }
}

// ---------------- main persistent recurrent kernel (4-CTA cluster) ---------
// smem float offsets:
//   s_pH   0      (128*68 = 8704)
//   s_W    8704   (128*256 = 32768)
//   s_h    41472  (8*68 = 544)
//   s_kT2  42016  (128*20 = 2560)
//   s_part 44576  (2*4*128*8 = 8192)
//   s_hsqp 52768  (2*4*8 = 64)
//   mbar   52832  (2 x u64 = 4 floats)
#define SMEM_FLOATS 52836
#define SPART_B   (44576u * 4u)
#define SHSQP_B   (52768u * 4u)
#define SMBAR_B   (52832u * 4u)
#define PARTBUF_B 16384u          // 4*128*8*4 bytes
#define HSQBUF_B  128u            // 4*8*4 bytes

__global__ void __launch_bounds__(NTHR, 1) __cluster_dims__(GBLK, 1, 1)
qlstm_main(const float* __restrict__ proto,
           const float* __restrict__ Wf_, const float* __restrict__ bf_,
           const float* __restrict__ Wi_, const float* __restrict__ bi_,
           const float* __restrict__ Wg_, const float* __restrict__ bg_,
           const float* __restrict__ Wo_, const float* __restrict__ bo_,
           float* __restrict__ out) {
    extern __shared__ float sm[];
    float* s_pH   = sm;                 // [128 p][68] own 64-j slice of protoH
    float* s_W    = sm + 8704;          // [p][ul*4+gate], 256 cols
    float* s_h    = sm + 41472;         // [8 rows][68] own 64-j slice (local!)
    float* s_kT2  = sm + 42016;         // [p][row*2] duplicated k, pitch 20
    float* s_part = sm + 44576;         // [2][4 src][128 p][8 rows]
    float* s_hsqp = sm + 52768;         // [2][4 src][8 rows]

    const int tid = threadIdx.x;
    uint32_t sub_u, grp_u;
    asm("mov.u32 %0, %%cluster_ctarank;" : "=r"(sub_u));
    asm("mov.u32 %0, %%clusterid.x;"     : "=r"(grp_u));
    const int sub = (int)sub_u;   // j-chunk / unit-chunk (64 wide)
    const int grp = (int)grp_u;   // batch group 0..31 (8 rows each)

    // phase-1 / reduce mapping: thread -> (p, 4 rows)
    const int p1p = tid >> 1;          // 0..127
    const int rh4 = tid & 1;           // rows rh4*4 .. rh4*4+3
    // phase-2 mapping: warp = 8 local units x 4 row-pairs
    const int w    = tid >> 5;
    const int lane = tid & 31;
    const int ul   = w * 8 + (lane & 7);     // local unit 0..63
    const int rp   = lane >> 3;              // 0..3
    const int row0 = rp * 2;                 // even row
    const int gu   = sub * 64 + ul;          // global unit
    const int idx0 = (grp * 8 + row0) * H_ + gu;
    const int idx1 = idx0 + H_;

    // ---- persistent SMEM fills ----
    for (int i = tid; i < 128 * 64; i += NTHR) {
        int p = i >> 6, j = i & 63;
        s_pH[p * 68 + j] = proto[(size_t)p * (D_ + H_) + D_ + sub * 64 + j];
    }
#pragma unroll
    for (int g = 0; g < 4; g++) {
        const float* Wp = (g == 0) ? Wf_ : (g == 1) ? Wi_ : (g == 2) ? Wg_ : Wo_;
        for (int i = tid; i < 128 * 64; i += NTHR) {
            int p = i & 127, u = i >> 7;
            s_W[p * 256 + u * 4 + g] = Wp[(size_t)(sub * 64 + u) * P_ + p];
        }
    }
    for (int i = tid; i < 8 * 68; i += NTHR) s_h[i] = 0.f;
    const ull bfi = pack2(bf_[gu], bi_[gu]);
    const ull bgo = pack2(bg_[gu], bo_[gu]);

    // ---- mbarrier init + one-time cluster rendezvous ----
    const uint32_t sbase = smem_u32(sm);
    if (tid == 0) {
        MBAR_INIT(sbase + SMBAR_B,     GBLK);
        MBAR_INIT(sbase + SMBAR_B + 8, GBLK);
    }
    __syncthreads();
    CLUSTER_SYNC();

    // ---- precompute remote DSMEM addresses (hoisted mapa) ----
    const uint32_t my_part_off = SPART_B +
        (uint32_t)((((sub * 128) + p1p) * 8 + rh4 * 4) * 4);
    const int hrow = tid >> 3;
    const uint32_t my_hsq_off = SHSQP_B + (uint32_t)((sub * 8 + hrow) * 4);
    uint32_t part_dst[GBLK], hsq_dst[GBLK], bar_rem[GBLK];
#pragma unroll
    for (int r = 0; r < GBLK; r++) {
        uint32_t rb = mapa_u32(sbase, (uint32_t)r);
        part_dst[r] = rb + my_part_off;
        hsq_dst[r]  = rb + my_hsq_off;
        bar_rem[r]  = rb + SMBAR_B;
    }

    float c0 = 0.f, c1 = 0.f, h0v = 0.f, h1v = 0.f;
    const size_t OUT_H = (size_t)T_ * BH_;

    // prefetch A(0) for this thread's (p, 4 rows)
    float a_cur[4];
#pragma unroll
    for (int r = 0; r < 4; r++)
        a_cur[r] = __ldcg(&g_A[(size_t)(grp * 8 + rh4 * 4 + r) * P_ + p1p]);

    unsigned pc0 = 0, pc1 = 0;   // per-buffer parity counters
    __syncthreads();

#pragma unroll 1
    for (int t = 0; t < T_; t++) {
        const int buf = t & 1;
        float dsum[4] = {0.f, 0.f, 0.f, 0.f};
        float hh4[4]  = {0.f, 0.f, 0.f, 0.f};

        if (t > 0) {
            // ===== phase 1: partial dots over own 64 j's, all 128 p =====
            {
                const ulonglong2* pp = (const ulonglong2*)&s_pH[p1p * 68];
                ull accA[4], accB[4];
#pragma unroll
                for (int r = 0; r < 4; r++) { accA[r] = 0ull; accB[r] = 0ull; }
#pragma unroll 4
                for (int jc = 0; jc < 16; jc++) {
                    ulonglong2 pv = pp[jc];
#pragma unroll
                    for (int r = 0; r < 4; r++) {
                        ulonglong2 hv = *(const ulonglong2*)
                            &s_h[(rh4 * 4 + r) * 68 + jc * 4];
                        accA[r] = fma2(hv.x, pv.x, accA[r]);
                        accB[r] = fma2(hv.y, pv.y, accB[r]);
                    }
                }
                float pw[4];
#pragma unroll
                for (int r = 0; r < 4; r++) {
                    float x0, x1, x2, x3;
                    unpack2(accA[r], x0, x1);
                    unpack2(accB[r], x2, x3);
                    pw[r] = (x0 + x1) + (x2 + x3);
                }
                // broadcast partial slice to all 4 CTAs' s_part
                ull lo = pack2(pw[0], pw[1]);
                ull hi = pack2(pw[2], pw[3]);
                const uint32_t boff = buf ? PARTBUF_B : 0u;
#pragma unroll
                for (int r = 0; r < GBLK; r++) {
                    asm volatile("st.shared::cluster.b64 [%0], %1;"
                                 :: "r"(part_dst[r] + boff), "l"(lo) : "memory");
                    asm volatile("st.shared::cluster.b64 [%0], %1;"
                                 :: "r"(part_dst[r] + boff + 8u), "l"(hi) : "memory");
                }
            }
            // ===== partial |h|^2 over own 64 j =====
            if (tid < 64) {
                int seg = (tid & 7) * 8;
                const float* hr = &s_h[hrow * 68 + seg];
                float ss = 0.f;
#pragma unroll
                for (int j = 0; j < 8; j++) ss += hr[j] * hr[j];
#pragma unroll
                for (int o = 4; o; o >>= 1)
                    ss += __shfl_down_sync(0xffffffffu, ss, o, 8);
                if ((tid & 7) == 0) {
                    const uint32_t boff2 = buf ? HSQBUF_B : 0u;
#pragma unroll
                    for (int r = 0; r < GBLK; r++)
                        asm volatile("st.shared::cluster.b32 [%0], %1;"
                                     :: "r"(hsq_dst[r] + boff2), "f"(ss) : "memory");
                }
            }
            __syncthreads();   // all this CTA's remote stores issued
            if (tid == 0) {
#pragma unroll
                for (int r = 0; r < GBLK; r++)
                    MBAR_ARRIVE_REMOTE(bar_rem[r] + (unsigned)buf * 8u);
            }
            // ===== wait for all 4 partial slices =====
            {
                unsigned par = buf ? (pc1 & 1u) : (pc0 & 1u);
                mbar_wait_cluster(sbase + SMBAR_B + (unsigned)buf * 8u, par);
                if (buf) pc1 ^= 1u; else pc0 ^= 1u;
            }
            // ===== local reduce (pure SMEM) =====
            {
                const float4* pb = (const float4*)(s_part + (buf ? 4096 : 0));
                float4 u0 = pb[(0 * 128 + p1p) * 2 + rh4];
                float4 u1 = pb[(1 * 128 + p1p) * 2 + rh4];
                float4 u2 = pb[(2 * 128 + p1p) * 2 + rh4];
                float4 u3 = pb[(3 * 128 + p1p) * 2 + rh4];
                dsum[0] = (u0.x + u1.x) + (u2.x + u3.x);
                dsum[1] = (u0.y + u1.y) + (u2.y + u3.y);
                dsum[2] = (u0.z + u1.z) + (u2.z + u3.z);
                dsum[3] = (u0.w + u1.w) + (u2.w + u3.w);
                const float* hq = s_hsqp + (buf ? 32 : 0);
#pragma unroll
                for (int r = 0; r < 4; r++) {
                    int rw = rh4 * 4 + r;
                    hh4[r] = (hq[0 * 8 + rw] + hq[1 * 8 + rw]) +
                             (hq[2 * 8 + rw] + hq[3 * 8 + rw]);
                }
            }
        }

        // ===== assemble k and write duplicated layout =====
        {
            float kv[4];
#pragma unroll
            for (int r = 0; r < 4; r++) {
                float d2 = (t > 0)
                    ? (a_cur[r] + hh4[r] - 2.f * dsum[r])
                    : a_cur[r];
                kv[r] = __expf(-d2);
            }
            float4* dst = (float4*)&s_kT2[p1p * 20 + rh4 * 8];
            dst[0] = make_float4(kv[0], kv[0], kv[1], kv[1]);
            dst[1] = make_float4(kv[2], kv[2], kv[3], kv[3]);
        }
        // prefetch A(t+1) — latency hidden under the GEMM
        {
            int tn = (t + 1 < T_) ? (t + 1) : (T_ - 1);
#pragma unroll
            for (int r = 0; r < 4; r++)
                a_cur[r] = __ldcg(&g_A[(size_t)tn * B_ * P_ +
                                       (size_t)(grp * 8 + rh4 * 4 + r) * P_ + p1p]);
        }
        __syncthreads();

        // ===== phase 2: gate GEMM + state update (h stays local) =====
        {
            ull afi0 = bfi, ago0 = bgo, afi1 = bfi, ago1 = bgo;
            const float* kbase = &s_kT2[row0 * 2];
            const float* wbase = &s_W[ul * 4];
#pragma unroll 8
            for (int p = 0; p < 128; p++) {
                ulonglong2 w2 = *(const ulonglong2*)(wbase + p * 256);
                ulonglong2 kk = *(const ulonglong2*)(kbase + p * 20);
                afi0 = fma2(kk.x, w2.x, afi0);
                ago0 = fma2(kk.x, w2.y, ago0);
                afi1 = fma2(kk.y, w2.x, afi1);
                ago1 = fma2(kk.y, w2.y, ago1);
            }
            float vf, vi, vg, vo;
            unpack2(afi0, vf, vi); unpack2(ago0, vg, vo);
            {
                float f = sigf(vf), ii = sigf(vi), gg = tanh_fast(vg), o = sigf(vo);
                c0 = f * c0 + ii * gg;
                h0v = o * tanh_fast(c0);
                s_h[row0 * 68 + ul] = h0v;
            }
            unpack2(afi1, vf, vi); unpack2(ago1, vg, vo);
            {
                float f = sigf(vf), ii = sigf(vi), gg = tanh_fast(vg), o = sigf(vo);
                c1 = f * c1 + ii * gg;
                h1v = o * tanh_fast(c1);
                s_h[(row0 + 1) * 68 + ul] = h1v;
            }
            out[(size_t)t * BH_ + idx0] = h0v;
            out[(size_t)t * BH_ + idx1] = h1v;
        }
        __syncthreads();   // h complete before next phase1 reads s_h
    }

    // final hx / cx
    out[OUT_H + idx0] = h0v;
    out[OUT_H + BH_ + idx0] = c0;
    out[OUT_H + idx1] = h1v;
    out[OUT_H + BH_ + idx1] = c1;
}

// ---------------- launch ----------------------------------------------------
extern "C" void kernel_launch(void* const* d_in, const int* in_sizes, int n_in,
                              void* d_out, int out_size) {
    const float* x     = (const float*)d_in[0];
    const float* proto = (const float*)d_in[1];
    const float* Wf    = (const float*)d_in[2];
    const float* bf    = (const float*)d_in[3];
    const float* Wi    = (const float*)d_in[4];
    const float* bi    = (const float*)d_in[5];
    const float* Wg    = (const float*)d_in[6];
    const float* bg    = (const float*)d_in[7];
    const float* Wo    = (const float*)d_in[8];
    const float* bo    = (const float*)d_in[9];
    float* out = (float*)d_out;

    const int smem_bytes = SMEM_FLOATS * (int)sizeof(float);
    cudaFuncSetAttribute(qlstm_main, cudaFuncAttributeMaxDynamicSharedMemorySize,
                         smem_bytes);

    xsq_kernel<<<M_ / 8, 256>>>(x);
    psum_kernel<<<1, 128>>>(proto);
    agemm_kernel<<<M_ / 64, 256>>>(x, proto);
    qlstm_main<<<NBLK, NTHR, smem_bytes>>>(proto, Wf, bf, Wi, bi, Wg, bg, Wo, bo, out);
}

// round 10
// speedup vs baseline: 1.1049x; 1.1049x over previous
#include <cuda_runtime.h>
#include <cstdint>

#define T_ 512
#define B_ 256
#define D_ 128
#define H_ 256
#define P_ 128
#define M_ (T_*B_)
#define NBLK 128
#define NTHR 256
#define BH_ (B_*H_)
#define NGRP 32           // 32 groups x 4 blocks, 8 batch rows each
#define GBLK 4
#define SLICE_F 1040      // per-slice floats: 128p*8rows + 8 hsq + pad (16B mult)

typedef unsigned long long ull;

// ---------------- scratch ---------------------------------------------------
__device__ float g_A[(size_t)T_*B_*P_];          // precomputed x-part of distance
__device__ float g_xsq[M_];
__device__ float g_psum[P_];
__device__ float g_part[2*NGRP*GBLK*SLICE_F];    // double-buffered partial dots+hsq
__device__ unsigned int g_cnt[NGRP*32];          // 1 barrier counter per group

// ---------------- f32x2 helpers --------------------------------------------
__device__ __forceinline__ ull pack2(float lo, float hi) {
    ull r; asm("mov.b64 %0, {%1, %2};" : "=l"(r) : "f"(lo), "f"(hi)); return r;
}
__device__ __forceinline__ void unpack2(ull v, float& lo, float& hi) {
    asm("mov.b64 {%0, %1}, %2;" : "=f"(lo), "=f"(hi) : "l"(v));
}
__device__ __forceinline__ ull fma2(ull a, ull b, ull c) {
    ull d; asm("fma.rn.f32x2 %0, %1, %2, %3;" : "=l"(d) : "l"(a), "l"(b), "l"(c));
    return d;
}
__device__ __forceinline__ float sigf(float x) {
    return __fdividef(1.f, 1.f + __expf(-x));
}
__device__ __forceinline__ float tanh_fast(float x) {
    float e = __expf(2.f * x);
    return 1.f - __fdividef(2.f, e + 1.f);
}

// ---------------- precompute: row norms of x -------------------------------
__global__ void xsq_kernel(const float* __restrict__ x) {
    int warp = (blockIdx.x * blockDim.x + threadIdx.x) >> 5;
    int lane = threadIdx.x & 31;
    if (warp >= M_) return;
    const float* row = x + (size_t)warp * D_;
    float s = 0.f;
#pragma unroll
    for (int i = 0; i < 4; i++) { float v = row[lane + 32*i]; s += v*v; }
#pragma unroll
    for (int o = 16; o; o >>= 1) s += __shfl_down_sync(0xffffffffu, s, o);
    if (lane == 0) g_xsq[warp] = s;
}

// ---------------- precompute: full row norms of prototypes -----------------
__global__ void psum_kernel(const float* __restrict__ proto) {
    int p = threadIdx.x;
    if (p >= P_) return;
    const float* row = proto + (size_t)p * (D_ + H_);
    float s = 0.f;
    for (int i = 0; i < D_ + H_; i++) { float v = row[i]; s += v*v; }
    g_psum[p] = s;
}

// ---------------- precompute GEMM: A[t,b,p] = xsq + psum - 2*x.px ----------
__global__ void agemm_kernel(const float* __restrict__ x,
                             const float* __restrict__ proto) {
    __shared__ float sX[64][33];
    __shared__ float sP[32][132];
    const int tid = threadIdx.x;
    const int tx = tid & 31;
    const int ty = tid >> 5;
    const int m0 = blockIdx.x * 64;

    float acc[8][4];
#pragma unroll
    for (int r = 0; r < 8; r++)
#pragma unroll
        for (int q = 0; q < 4; q++) acc[r][q] = 0.f;

    for (int k0 = 0; k0 < D_; k0 += 32) {
#pragma unroll
        for (int i = 0; i < 8; i++) {
            int e = tid + i * 256;
            int r = e >> 5, c = e & 31;
            sX[r][c] = x[(size_t)(m0 + r) * D_ + k0 + c];
        }
#pragma unroll
        for (int i = 0; i < 16; i++) {
            int e = tid + i * 256;
            int p = e >> 5, c = e & 31;
            sP[c][p] = proto[(size_t)p * (D_ + H_) + k0 + c];
        }
        __syncthreads();
#pragma unroll
        for (int kc = 0; kc < 32; kc++) {
            float4 b4 = *(const float4*)&sP[kc][tx * 4];
#pragma unroll
            for (int r = 0; r < 8; r++) {
                float a = sX[ty * 8 + r][kc];
                acc[r][0] += a * b4.x; acc[r][1] += a * b4.y;
                acc[r][2] += a * b4.z; acc[r][3] += a * b4.w;
            }
        }
        __syncthreads();
    }
#pragma unroll
    for (int r = 0; r < 8; r++) {
        int row = m0 + ty * 8 + r;
        float xs = g_xsq[row];
        float4 o;
        o.x = xs + g_psum[tx*4+0] - 2.f * acc[r][0];
        o.y = xs + g_psum[tx*4+1] - 2.f * acc[r][1];
        o.z = xs + g_psum[tx*4+2] - 2.f * acc[r][2];
        o.w = xs + g_psum[tx*4+3] - 2.f * acc[r][3];
        *(float4*)&g_A[(size_t)row * P_ + tx * 4] = o;
    }
}

// ---------------- counter reset (graph replay determinism) -----------------
__global__ void zero_cnt_kernel() {
    int i = threadIdx.x;
    if (i < NGRP*32) g_cnt[i] = 0;
}

// ---------------- split group barrier --------------------------------------
__device__ __forceinline__ void bar_arrive(unsigned int* cnt) {
    __syncthreads();
    if (threadIdx.x == 0)
        asm volatile("red.release.gpu.global.add.u32 [%0], 1;"
                     :: "l"(cnt) : "memory");
}
__device__ __forceinline__ void bar_wait(unsigned int* cnt, unsigned int target) {
    if (threadIdx.x == 0) {
        unsigned int v;
        do {
            asm volatile("ld.acquire.gpu.global.u32 %0, [%1];"
                         : "=r"(v) : "l"(cnt) : "memory");
        } while (v < target);
    }
    __syncthreads();
}

// ---------------- main persistent recurrent kernel -------------------------
// smem floats: s_pH 128*68 | s_W 128*256 | s_h 8*68 | s_kT2 128*20
#define SMEM_FLOATS (8704 + 32768 + 544 + 2560)

__global__ void __launch_bounds__(NTHR, 1)
qlstm_main(const float* __restrict__ proto,
           const float* __restrict__ Wf_, const float* __restrict__ bf_,
           const float* __restrict__ Wi_, const float* __restrict__ bi_,
           const float* __restrict__ Wg_, const float* __restrict__ bg_,
           const float* __restrict__ Wo_, const float* __restrict__ bo_,
           float* __restrict__ out) {
    extern __shared__ float sm[];
    float* s_pH   = sm;                    // [128 p][68] own 64-j slice of protoH
    float* s_W    = s_pH + 128 * 68;       // [p][ul*4+gate], 256 cols
    float* s_h    = s_W + 128 * 256;       // [8 rows][68] own 64-j slice (local!)
    float* s_kT2  = s_h + 8 * 68;          // [p][row*2] duplicated k, pitch 20

    const int tid = threadIdx.x;
    const int bid = blockIdx.x;
    const int grp = bid >> 2;   // batch group 0..31 (8 rows each)
    const int sub = bid & 3;    // j-chunk / unit-chunk (64 wide)

    // phase-1 / reduce mapping: thread -> (p, 4 rows)
    const int p1p = tid >> 1;          // 0..127
    const int rh4 = tid & 1;           // rows rh4*4 .. rh4*4+3
    // phase-2 mapping: warp = 8 local units x 4 row-pairs
    const int w    = tid >> 5;
    const int lane = tid & 31;
    const int ul   = w * 8 + (lane & 7);     // local unit 0..63
    const int rp   = lane >> 3;              // 0..3
    const int row0 = rp * 2;                 // even row
    const int gu   = sub * 64 + ul;          // global unit
    const int idx0 = (grp * 8 + row0) * H_ + gu;
    const int idx1 = idx0 + H_;

    // ---- persistent SMEM fills ----
    for (int i = tid; i < 128 * 64; i += NTHR) {
        int p = i >> 6, j = i & 63;
        s_pH[p * 68 + j] = proto[(size_t)p * (D_ + H_) + D_ + sub * 64 + j];
    }
#pragma unroll
    for (int g = 0; g < 4; g++) {
        const float* Wp = (g == 0) ? Wf_ : (g == 1) ? Wi_ : (g == 2) ? Wg_ : Wo_;
        for (int i = tid; i < 128 * 64; i += NTHR) {
            int p = i & 127, u = i >> 7;
            s_W[p * 256 + u * 4 + g] = Wp[(size_t)(sub * 64 + u) * P_ + p];
        }
    }
    for (int i = tid; i < 8 * 68; i += NTHR) s_h[i] = 0.f;
    const ull bfi = pack2(bf_[gu], bi_[gu]);
    const ull bgo = pack2(bg_[gu], bo_[gu]);

    float c0 = 0.f, c1 = 0.f, h0v = 0.f, h1v = 0.f;

    unsigned int* cnt = &g_cnt[grp * 32];
    const size_t OUT_H = (size_t)T_ * BH_;

    // prefetch A(0) for this thread's (p, 4 rows)
    float a_cur[4];
#pragma unroll
    for (int r = 0; r < 4; r++)
        a_cur[r] = __ldcg(&g_A[(size_t)(grp * 8 + rh4 * 4 + r) * P_ + p1p]);

    __syncthreads();

#pragma unroll 1
    for (int t = 0; t < T_; t++) {
        const int buf = t & 1;
        float dsum[4] = {0.f, 0.f, 0.f, 0.f};
        float hh4[4]  = {0.f, 0.f, 0.f, 0.f};

        if (t > 0) {
            float* myslice = &g_part[(((size_t)buf * NGRP + grp) * GBLK + sub)
                                     * SLICE_F];
            // ===== phase 1: partial dots over own 64 j's, all 128 p =====
            {
                const ulonglong2* pp = (const ulonglong2*)&s_pH[p1p * 68];
                ull accA[4], accB[4];
#pragma unroll
                for (int r = 0; r < 4; r++) { accA[r] = 0ull; accB[r] = 0ull; }
#pragma unroll 4
                for (int jc = 0; jc < 16; jc++) {
                    ulonglong2 pv = pp[jc];
#pragma unroll
                    for (int r = 0; r < 4; r++) {
                        ulonglong2 hv = *(const ulonglong2*)
                            &s_h[(rh4 * 4 + r) * 68 + jc * 4];
                        accA[r] = fma2(hv.x, pv.x, accA[r]);
                        accB[r] = fma2(hv.y, pv.y, accB[r]);
                    }
                }
                float4 pw;
                float* pwf = (float*)&pw;
#pragma unroll
                for (int r = 0; r < 4; r++) {
                    float x0, x1, x2, x3;
                    unpack2(accA[r], x0, x1);
                    unpack2(accB[r], x2, x3);
                    pwf[r] = (x0 + x1) + (x2 + x3);
                }
                *(float4*)&myslice[p1p * 8 + rh4 * 4] = pw;
            }
            // ===== partial |h|^2 over own 64 j -> slice tail =====
            if (tid < 64) {
                int row = tid >> 3, seg = (tid & 7) * 8;
                const float* hr = &s_h[row * 68 + seg];
                float ss = 0.f;
#pragma unroll
                for (int j = 0; j < 8; j++) ss += hr[j] * hr[j];
#pragma unroll
                for (int o = 4; o; o >>= 1)
                    ss += __shfl_down_sync(0xffffffffu, ss, o, 8);
                if ((tid & 7) == 0)
                    myslice[1024 + row] = ss;
            }
            bar_arrive(cnt);
            bar_wait(cnt, 4u * (unsigned)t);

            // ===== fused reduce: partials + hsq in one MLP=8 LDG batch =====
            {
                const float* base =
                    &g_part[(((size_t)buf * NGRP + grp) * GBLK) * SLICE_F];
                float4 u[GBLK], hq[GBLK];
#pragma unroll
                for (int s = 0; s < GBLK; s++) {
                    u[s]  = __ldcg((const float4*)(base + s * SLICE_F
                                                   + p1p * 8 + rh4 * 4));
                    hq[s] = __ldcg((const float4*)(base + s * SLICE_F
                                                   + 1024 + rh4 * 4));
                }
                dsum[0] = (u[0].x + u[1].x) + (u[2].x + u[3].x);
                dsum[1] = (u[0].y + u[1].y) + (u[2].y + u[3].y);
                dsum[2] = (u[0].z + u[1].z) + (u[2].z + u[3].z);
                dsum[3] = (u[0].w + u[1].w) + (u[2].w + u[3].w);
                hh4[0]  = (hq[0].x + hq[1].x) + (hq[2].x + hq[3].x);
                hh4[1]  = (hq[0].y + hq[1].y) + (hq[2].y + hq[3].y);
                hh4[2]  = (hq[0].z + hq[1].z) + (hq[2].z + hq[3].z);
                hh4[3]  = (hq[0].w + hq[1].w) + (hq[2].w + hq[3].w);
            }
        }

        // ===== assemble k and write duplicated layout (no staging sync) =====
        {
            float kv[4];
#pragma unroll
            for (int r = 0; r < 4; r++) {
                float d2 = (t > 0)
                    ? (a_cur[r] + hh4[r] - 2.f * dsum[r])
                    : a_cur[r];
                kv[r] = __expf(-d2);
            }
            float4* dst = (float4*)&s_kT2[p1p * 20 + rh4 * 8];
            dst[0] = make_float4(kv[0], kv[0], kv[1], kv[1]);
            dst[1] = make_float4(kv[2], kv[2], kv[3], kv[3]);
        }
        // prefetch A(t+1) — latency hidden under the GEMM
        {
            int tn = (t + 1 < T_) ? (t + 1) : (T_ - 1);
#pragma unroll
            for (int r = 0; r < 4; r++)
                a_cur[r] = __ldcg(&g_A[(size_t)tn * B_ * P_ +
                                       (size_t)(grp * 8 + rh4 * 4 + r) * P_ + p1p]);
        }
        __syncthreads();

        // ===== phase 2: gate GEMM + state update (h stays local) =====
        {
            ull afi0 = bfi, ago0 = bgo, afi1 = bfi, ago1 = bgo;
            const float* kbase = &s_kT2[row0 * 2];
            const float* wbase = &s_W[ul * 4];
#pragma unroll 8
            for (int p = 0; p < 128; p++) {
                ulonglong2 w2 = *(const ulonglong2*)(wbase + p * 256);
                ulonglong2 kk = *(const ulonglong2*)(kbase + p * 20);
                afi0 = fma2(kk.x, w2.x, afi0);
                ago0 = fma2(kk.x, w2.y, ago0);
                afi1 = fma2(kk.y, w2.x, afi1);
                ago1 = fma2(kk.y, w2.y, ago1);
            }
            float vf, vi, vg, vo;
            unpack2(afi0, vf, vi); unpack2(ago0, vg, vo);
            {
                float f = sigf(vf), ii = sigf(vi), gg = tanh_fast(vg), o = sigf(vo);
                c0 = f * c0 + ii * gg;
                h0v = o * tanh_fast(c0);
                s_h[row0 * 68 + ul] = h0v;
            }
            unpack2(afi1, vf, vi); unpack2(ago1, vg, vo);
            {
                float f = sigf(vf), ii = sigf(vi), gg = tanh_fast(vg), o = sigf(vo);
                c1 = f * c1 + ii * gg;
                h1v = o * tanh_fast(c1);
                s_h[(row0 + 1) * 68 + ul] = h1v;
            }
            out[(size_t)t * BH_ + idx0] = h0v;
            out[(size_t)t * BH_ + idx1] = h1v;
        }
        __syncthreads();   // h complete before next phase1 reads s_h
    }

    // final hx / cx
    out[OUT_H + idx0] = h0v;
    out[OUT_H + BH_ + idx0] = c0;
    out[OUT_H + idx1] = h1v;
    out[OUT_H + BH_ + idx1] = c1;
}

// ---------------- launch ----------------------------------------------------
extern "C" void kernel_launch(void* const* d_in, const int* in_sizes, int n_in,
                              void* d_out, int out_size) {
    const float* x     = (const float*)d_in[0];
    const float* proto = (const float*)d_in[1];
    const float* Wf    = (const float*)d_in[2];
    const float* bf    = (const float*)d_in[3];
    const float* Wi    = (const float*)d_in[4];
    const float* bi    = (const float*)d_in[5];
    const float* Wg    = (const float*)d_in[6];
    const float* bg    = (const float*)d_in[7];
    const float* Wo    = (const float*)d_in[8];
    const float* bo    = (const float*)d_in[9];
    float* out = (float*)d_out;

    const int smem_bytes = SMEM_FLOATS * (int)sizeof(float);
    cudaFuncSetAttribute(qlstm_main, cudaFuncAttributeMaxDynamicSharedMemorySize,
                         smem_bytes);

    zero_cnt_kernel<<<1, 1024>>>();
    xsq_kernel<<<M_ / 8, 256>>>(x);
    psum_kernel<<<1, 128>>>(proto);
    agemm_kernel<<<M_ / 64, 256>>>(x, proto);
    qlstm_main<<<NBLK, NTHR, smem_bytes>>>(proto, Wf, bf, Wi, bi, Wg, bg, Wo, bo, out);
}

// round 11
// speedup vs baseline: 1.1327x; 1.0251x over previous
#include <cuda_runtime.h>
#include <cstdint>

#define T_ 512
#define B_ 256
#define D_ 128
#define H_ 256
#define P_ 128
#define M_ (T_*B_)
#define NBLK 128
#define NTHR 256
#define BH_ (B_*H_)
#define NGRP 32           // 32 groups x 4 blocks, 8 batch rows each
#define GBLK 4
#define SLICE_F 528       // per (CTA,team) slice: 128p*4rows + 4 hsq + pad

typedef unsigned long long ull;

// ---------------- scratch ---------------------------------------------------
__device__ float g_A[(size_t)T_*B_*P_];          // precomputed x-part of distance
__device__ float g_xsq[M_];
__device__ float g_psum[P_];
__device__ float g_part[2*NGRP*2*GBLK*SLICE_F];  // [buf][grp][team][cta][slice]
__device__ unsigned int g_cnt[NGRP*2*32];        // counter per (group, team)

// ---------------- f32x2 helpers --------------------------------------------
__device__ __forceinline__ ull pack2(float lo, float hi) {
    ull r; asm("mov.b64 %0, {%1, %2};" : "=l"(r) : "f"(lo), "f"(hi)); return r;
}
__device__ __forceinline__ void unpack2(ull v, float& lo, float& hi) {
    asm("mov.b64 {%0, %1}, %2;" : "=f"(lo), "=f"(hi) : "l"(v));
}
__device__ __forceinline__ ull fma2(ull a, ull b, ull c) {
    ull d; asm("fma.rn.f32x2 %0, %1, %2, %3;" : "=l"(d) : "l"(a), "l"(b), "l"(c));
    return d;
}
__device__ __forceinline__ float sigf(float x) {
    return __fdividef(1.f, 1.f + __expf(-x));
}
__device__ __forceinline__ float tanh_fast(float x) {
    float e = __expf(2.f * x);
    return 1.f - __fdividef(2.f, e + 1.f);
}
__device__ __forceinline__ void bar_named(int id) {
    asm volatile("bar.sync %0, 128;" :: "r"(id) : "memory");
}

// ---------------- precompute: row norms of x -------------------------------
__global__ void xsq_kernel(const float* __restrict__ x) {
    int warp = (blockIdx.x * blockDim.x + threadIdx.x) >> 5;
    int lane = threadIdx.x & 31;
    if (warp >= M_) return;
    const float* row = x + (size_t)warp * D_;
    float s = 0.f;
#pragma unroll
    for (int i = 0; i < 4; i++) { float v = row[lane + 32*i]; s += v*v; }
#pragma unroll
    for (int o = 16; o; o >>= 1) s += __shfl_down_sync(0xffffffffu, s, o);
    if (lane == 0) g_xsq[warp] = s;
}

// ---------------- precompute: full row norms of prototypes -----------------
__global__ void psum_kernel(const float* __restrict__ proto) {
    int p = threadIdx.x;
    if (p >= P_) return;
    const float* row = proto + (size_t)p * (D_ + H_);
    float s = 0.f;
    for (int i = 0; i < D_ + H_; i++) { float v = row[i]; s += v*v; }
    g_psum[p] = s;
}

// ---------------- precompute GEMM: A[t,b,p] = xsq + psum - 2*x.px ----------
__global__ void agemm_kernel(const float* __restrict__ x,
                             const float* __restrict__ proto) {
    __shared__ float sX[64][33];
    __shared__ float sP[32][132];
    const int tid = threadIdx.x;
    const int tx = tid & 31;
    const int ty = tid >> 5;
    const int m0 = blockIdx.x * 64;

    float acc[8][4];
#pragma unroll
    for (int r = 0; r < 8; r++)
#pragma unroll
        for (int q = 0; q < 4; q++) acc[r][q] = 0.f;

    for (int k0 = 0; k0 < D_; k0 += 32) {
#pragma unroll
        for (int i = 0; i < 8; i++) {
            int e = tid + i * 256;
            int r = e >> 5, c = e & 31;
            sX[r][c] = x[(size_t)(m0 + r) * D_ + k0 + c];
        }
#pragma unroll
        for (int i = 0; i < 16; i++) {
            int e = tid + i * 256;
            int p = e >> 5, c = e & 31;
            sP[c][p] = proto[(size_t)p * (D_ + H_) + k0 + c];
        }
        __syncthreads();
#pragma unroll
        for (int kc = 0; kc < 32; kc++) {
            float4 b4 = *(const float4*)&sP[kc][tx * 4];
#pragma unroll
            for (int r = 0; r < 8; r++) {
                float a = sX[ty * 8 + r][kc];
                acc[r][0] += a * b4.x; acc[r][1] += a * b4.y;
                acc[r][2] += a * b4.z; acc[r][3] += a * b4.w;
            }
        }
        __syncthreads();
    }
#pragma unroll
    for (int r = 0; r < 8; r++) {
        int row = m0 + ty * 8 + r;
        float xs = g_xsq[row];
        float4 o;
        o.x = xs + g_psum[tx*4+0] - 2.f * acc[r][0];
        o.y = xs + g_psum[tx*4+1] - 2.f * acc[r][1];
        o.z = xs + g_psum[tx*4+2] - 2.f * acc[r][2];
        o.w = xs + g_psum[tx*4+3] - 2.f * acc[r][3];
        *(float4*)&g_A[(size_t)row * P_ + tx * 4] = o;
    }
}

// ---------------- counter reset (graph replay determinism) -----------------
__global__ void zero_cnt_kernel() {
    int i = blockIdx.x * blockDim.x + threadIdx.x;
    if (i < NGRP*2*32) g_cnt[i] = 0;
}

// ---------------- main persistent recurrent kernel -------------------------
// smem floats: s_pH 128*68 | s_W 128*256 | s_h 8*68 | s_kT2 128*20
#define SMEM_FLOATS (8704 + 32768 + 544 + 2560)

__global__ void __launch_bounds__(NTHR, 1)
qlstm_main(const float* __restrict__ proto,
           const float* __restrict__ Wf_, const float* __restrict__ bf_,
           const float* __restrict__ Wi_, const float* __restrict__ bi_,
           const float* __restrict__ Wg_, const float* __restrict__ bg_,
           const float* __restrict__ Wo_, const float* __restrict__ bo_,
           float* __restrict__ out) {
    extern __shared__ float sm[];
    float* s_pH   = sm;                    // [128 p][68] own 64-j slice of protoH
    float* s_W    = s_pH + 128 * 68;       // [p][ul*4+gate], 256 cols
    float* s_h    = s_W + 128 * 256;       // [8 rows][68] own 64-j slice
    float* s_kT2  = s_h + 8 * 68;          // [p][row*2] duplicated k, pitch 20

    const int tid = threadIdx.x;
    const int bid = blockIdx.x;
    const int grp = bid >> 2;       // batch group 0..31 (8 rows)
    const int sub = bid & 3;        // j-chunk / unit-chunk (64 wide)
    const int tm  = tid >> 7;       // team 0: rows 0-3, team 1: rows 4-7
    const int tt  = tid & 127;      // thread-in-team
    const int barid = tm + 1;       // named barrier id

    // phase-1 / reduce / exp role: thread -> p = tt, 4 team rows
    // phase-2 role: warp-in-team covers 16 units x 2 row-pairs
    const int wt   = tt >> 5;                 // warp in team 0..3
    const int lane = tid & 31;
    const int unit = wt * 16 + (lane & 15);   // local unit 0..63
    const int pair = lane >> 4;               // 0..1
    const int row0 = tm * 4 + pair * 2;       // even row 0..7
    const int gu   = sub * 64 + unit;         // global unit
    const int idx0 = (grp * 8 + row0) * H_ + gu;
    const int idx1 = idx0 + H_;

    // ---- persistent SMEM fills ----
    for (int i = tid; i < 128 * 64; i += NTHR) {
        int p = i >> 6, j = i & 63;
        s_pH[p * 68 + j] = proto[(size_t)p * (D_ + H_) + D_ + sub * 64 + j];
    }
#pragma unroll
    for (int g = 0; g < 4; g++) {
        const float* Wp = (g == 0) ? Wf_ : (g == 1) ? Wi_ : (g == 2) ? Wg_ : Wo_;
        for (int i = tid; i < 128 * 64; i += NTHR) {
            int p = i & 127, u = i >> 7;
            s_W[p * 256 + u * 4 + g] = Wp[(size_t)(sub * 64 + u) * P_ + p];
        }
    }
    for (int i = tid; i < 8 * 68; i += NTHR) s_h[i] = 0.f;
    const ull bfi = pack2(bf_[gu], bi_[gu]);
    const ull bgo = pack2(bg_[gu], bo_[gu]);
    __syncthreads();

    // ---- preload this thread's pH row into registers (64 floats) ----
    ull phr[32];
    {
        const ulonglong2* pr = (const ulonglong2*)&s_pH[tt * 68];
#pragma unroll
        for (int i = 0; i < 16; i++) {
            ulonglong2 v = pr[i];
            phr[2*i] = v.x; phr[2*i+1] = v.y;
        }
    }

    float c0 = 0.f, c1 = 0.f, h0v = 0.f, h1v = 0.f;
    unsigned int* cnt = &g_cnt[(grp * 2 + tm) * 32];
    const size_t OUT_H = (size_t)T_ * BH_;

    // prefetch A(0) for this thread's (p=tt, 4 team rows)
    float a_cur[4];
#pragma unroll
    for (int r = 0; r < 4; r++)
        a_cur[r] = __ldcg(&g_A[(size_t)(grp * 8 + tm * 4 + r) * P_ + tt]);

#pragma unroll 1
    for (int t = 0; t < T_; t++) {
        const int buf = t & 1;
        float dsum[4] = {0.f, 0.f, 0.f, 0.f};
        float hh4[4]  = {0.f, 0.f, 0.f, 0.f};

        if (t > 0) {
            float* myslice = &g_part[((((size_t)buf * NGRP + grp) * 2 + tm)
                                      * GBLK + sub) * SLICE_F];
            // ===== phase 1: partial dots (pH in regs, h broadcast LDS) =====
            {
                const ulonglong2* hr0 = (const ulonglong2*)&s_h[(tm*4+0) * 68];
                const ulonglong2* hr1 = (const ulonglong2*)&s_h[(tm*4+1) * 68];
                const ulonglong2* hr2 = (const ulonglong2*)&s_h[(tm*4+2) * 68];
                const ulonglong2* hr3 = (const ulonglong2*)&s_h[(tm*4+3) * 68];
                ull aA[4], aB[4];
#pragma unroll
                for (int r = 0; r < 4; r++) { aA[r] = 0ull; aB[r] = 0ull; }
#pragma unroll 4
                for (int jc = 0; jc < 16; jc++) {
                    ulonglong2 h0 = hr0[jc], h1 = hr1[jc];
                    ulonglong2 h2 = hr2[jc], h3 = hr3[jc];
                    aA[0] = fma2(h0.x, phr[2*jc],   aA[0]);
                    aB[0] = fma2(h0.y, phr[2*jc+1], aB[0]);
                    aA[1] = fma2(h1.x, phr[2*jc],   aA[1]);
                    aB[1] = fma2(h1.y, phr[2*jc+1], aB[1]);
                    aA[2] = fma2(h2.x, phr[2*jc],   aA[2]);
                    aB[2] = fma2(h2.y, phr[2*jc+1], aB[2]);
                    aA[3] = fma2(h3.x, phr[2*jc],   aA[3]);
                    aB[3] = fma2(h3.y, phr[2*jc+1], aB[3]);
                }
                float4 pw;
                float* pwf = (float*)&pw;
#pragma unroll
                for (int r = 0; r < 4; r++) {
                    float x0, x1, x2, x3;
                    unpack2(aA[r], x0, x1);
                    unpack2(aB[r], x2, x3);
                    pwf[r] = (x0 + x1) + (x2 + x3);
                }
                *(float4*)&myslice[tt * 4] = pw;
            }
            // ===== partial |h|^2 (32 threads per team) -> slice tail =====
            if (tt < 32) {
                int row = tt >> 3, seg = (tt & 7) * 8;
                const float* hr = &s_h[(tm * 4 + row) * 68 + seg];
                float ss = 0.f;
#pragma unroll
                for (int j = 0; j < 8; j++) ss += hr[j] * hr[j];
#pragma unroll
                for (int o = 4; o; o >>= 1)
                    ss += __shfl_down_sync(0xffffffffu, ss, o, 8);
                if ((tt & 7) == 0)
                    myslice[512 + row] = ss;
            }
            // ===== team arrive =====
            bar_named(barid);
            if (tt == 0)
                asm volatile("red.release.gpu.global.add.u32 [%0], 1;"
                             :: "l"(cnt) : "memory");
            // ===== team wait =====
            if (tt == 0) {
                unsigned int v, tgt = 4u * (unsigned)t;
                do {
                    asm volatile("ld.acquire.gpu.global.u32 %0, [%1];"
                                 : "=r"(v) : "l"(cnt) : "memory");
                } while (v < tgt);
            }
            bar_named(barid);

            // ===== fused reduce: 4 slices, partials + hsq, MLP=8 =====
            {
                const float* base = &g_part[((((size_t)buf * NGRP + grp) * 2 + tm)
                                             * GBLK) * SLICE_F];
                float4 u[GBLK], hq[GBLK];
#pragma unroll
                for (int s = 0; s < GBLK; s++) {
                    u[s]  = __ldcg((const float4*)(base + s * SLICE_F + tt * 4));
                    hq[s] = __ldcg((const float4*)(base + s * SLICE_F + 512));
                }
                dsum[0] = (u[0].x + u[1].x) + (u[2].x + u[3].x);
                dsum[1] = (u[0].y + u[1].y) + (u[2].y + u[3].y);
                dsum[2] = (u[0].z + u[1].z) + (u[2].z + u[3].z);
                dsum[3] = (u[0].w + u[1].w) + (u[2].w + u[3].w);
                hh4[0]  = (hq[0].x + hq[1].x) + (hq[2].x + hq[3].x);
                hh4[1]  = (hq[0].y + hq[1].y) + (hq[2].y + hq[3].y);
                hh4[2]  = (hq[0].z + hq[1].z) + (hq[2].z + hq[3].z);
                hh4[3]  = (hq[0].w + hq[1].w) + (hq[2].w + hq[3].w);
            }
        }

        // ===== assemble k, duplicated layout =====
        {
            float kv[4];
#pragma unroll
            for (int r = 0; r < 4; r++) {
                float d2 = (t > 0)
                    ? (a_cur[r] + hh4[r] - 2.f * dsum[r])
                    : a_cur[r];
                kv[r] = __expf(-d2);
            }
            float4* dst = (float4*)&s_kT2[tt * 20 + tm * 8];
            dst[0] = make_float4(kv[0], kv[0], kv[1], kv[1]);
            dst[1] = make_float4(kv[2], kv[2], kv[3], kv[3]);
        }
        // prefetch A(t+1) — latency hidden under the GEMM
        {
            int tn = (t + 1 < T_) ? (t + 1) : (T_ - 1);
#pragma unroll
            for (int r = 0; r < 4; r++)
                a_cur[r] = __ldcg(&g_A[(size_t)tn * B_ * P_ +
                                       (size_t)(grp * 8 + tm * 4 + r) * P_ + tt]);
        }
        bar_named(barid);   // team's kT2 half visible to team

        // ===== phase 2: gate GEMM + state update (team half) =====
        {
            ull afi0 = bfi, ago0 = bgo, afi1 = bfi, ago1 = bgo;
            const float* kbase = &s_kT2[row0 * 2];
            const float* wbase = &s_W[unit * 4];
#pragma unroll 8
            for (int p = 0; p < 128; p++) {
                ulonglong2 w2 = *(const ulonglong2*)(wbase + p * 256);
                ulonglong2 kk = *(const ulonglong2*)(kbase + p * 20);
                afi0 = fma2(kk.x, w2.x, afi0);
                ago0 = fma2(kk.x, w2.y, ago0);
                afi1 = fma2(kk.y, w2.x, afi1);
                ago1 = fma2(kk.y, w2.y, ago1);
            }
            float vf, vi, vg, vo;
            unpack2(afi0, vf, vi); unpack2(ago0, vg, vo);
            {
                float f = sigf(vf), ii = sigf(vi), gg = tanh_fast(vg), o = sigf(vo);
                c0 = f * c0 + ii * gg;
                h0v = o * tanh_fast(c0);
                s_h[row0 * 68 + unit] = h0v;
            }
            unpack2(afi1, vf, vi); unpack2(ago1, vg, vo);
            {
                float f = sigf(vf), ii = sigf(vi), gg = tanh_fast(vg), o = sigf(vo);
                c1 = f * c1 + ii * gg;
                h1v = o * tanh_fast(c1);
                s_h[(row0 + 1) * 68 + unit] = h1v;
            }
            out[(size_t)t * BH_ + idx0] = h0v;
            out[(size_t)t * BH_ + idx1] = h1v;
        }
        bar_named(barid);   // team's h visible before next phase1
    }

    // final hx / cx
    out[OUT_H + idx0] = h0v;
    out[OUT_H + BH_ + idx0] = c0;
    out[OUT_H + idx1] = h1v;
    out[OUT_H + BH_ + idx1] = c1;
}

// ---------------- launch ----------------------------------------------------
extern "C" void kernel_launch(void* const* d_in, const int* in_sizes, int n_in,
                              void* d_out, int out_size) {
    const float* x     = (const float*)d_in[0];
    const float* proto = (const float*)d_in[1];
    const float* Wf    = (const float*)d_in[2];
    const float* bf    = (const float*)d_in[3];
    const float* Wi    = (const float*)d_in[4];
    const float* bi    = (const float*)d_in[5];
    const float* Wg    = (const float*)d_in[6];
    const float* bg    = (const float*)d_in[7];
    const float* Wo    = (const float*)d_in[8];
    const float* bo    = (const float*)d_in[9];
    float* out = (float*)d_out;

    const int smem_bytes = SMEM_FLOATS * (int)sizeof(float);
    cudaFuncSetAttribute(qlstm_main, cudaFuncAttributeMaxDynamicSharedMemorySize,
                         smem_bytes);

    zero_cnt_kernel<<<2, 1024>>>();
    xsq_kernel<<<M_ / 8, 256>>>(x);
    psum_kernel<<<1, 128>>>(proto);
    agemm_kernel<<<M_ / 64, 256>>>(x, proto);
    qlstm_main<<<NBLK, NTHR, smem_bytes>>>(proto, Wf, bf, Wi, bi, Wg, bg, Wo, bo, out);
}